// round 3
// baseline (speedup 1.0000x reference)
#include <cuda_runtime.h>
#include <math.h>

// Closed-form collapse of the 4-qubit circuit:
//   m0 = cos(p4)cos(p0)cos(t0) - sin(p4)sin(t1+p1)sin(t0)
//   m1 = cos(t1+p1)cos(p0)cos(t0)
//   m2 = cos(t2)
//   m3 = cos(p3)cos(t2)cos(t3)
// logits[b,k] = sum_patch m.W[k] + bias[k]; out = log_softmax(logits).
//
// Launch: grid(5,64) x 256 threads. Each block handles 250 patch-pairs
// (500 patches) of one image; the last block to finish an image combines
// the 5 fixed-slot partials (deterministic order) and writes the output.

#define SL   5          // slices per image
#define PPSL 250        // patch-pairs per slice
#define BLKT 256

__device__ float2       g_partial[64 * SL];
__device__ unsigned int g_cnt[64];

__global__ __launch_bounds__(BLKT) void fused_kernel(
    const float* __restrict__ x,
    const float* __restrict__ W,
    const float* __restrict__ bias,
    const float* __restrict__ qp,
    float* __restrict__ out)
{
    const int tid   = threadIdx.x;
    const int slice = blockIdx.x;
    const int b     = blockIdx.y;

    // Per-thread circuit constants (uniform loads broadcast; overlaps x latency)
    float sp4, cp4;
    __sincosf(qp[4], &sp4, &cp4);
    const float cp0 = __cosf(qp[0]);
    const float cp3 = __cosf(qp[3]);
    const float P1  = qp[1];
    const float K1  = cp4 * cp0;

    float acc0 = 0.f, acc1 = 0.f;

    if (tid < PPSL) {
        const int q  = slice * PPSL + tid;   // pair index 0..1249
        const int i  = q / 25;               // patch row 0..49
        const int jp = q - i * 25;           // pair column 0..24

        const float* xb = x + b * 10000;
        const float4 r0 = *reinterpret_cast<const float4*>(xb + 200 * i + 4 * jp);
        const float4 r1 = *reinterpret_cast<const float4*>(xb + 200 * i + 100 + 4 * jp);
        const int pidx  = i * 50 + 2 * jp;
        const float4 wA0 = *reinterpret_cast<const float4*>(W + pidx * 4);
        const float4 wB0 = *reinterpret_cast<const float4*>(W + pidx * 4 + 4);
        const float4 wA1 = *reinterpret_cast<const float4*>(W + 10000 + pidx * 4);
        const float4 wB1 = *reinterpret_cast<const float4*>(W + 10000 + pidx * 4 + 4);

        // patch A: t = (r0.x, r0.y, r1.x, r1.y)
        {
            float s0, c0, sa, ca;
            __sincosf(r0.x, &s0, &c0);
            __sincosf(r0.y + P1, &sa, &ca);
            const float ct2 = __cosf(r1.x);
            const float ct3 = __cosf(r1.y);
            const float m0 = fmaf(K1, c0, -sp4 * sa * s0);
            const float m1 = cp0 * ca * c0;
            const float m3 = cp3 * ct2 * ct3;
            acc0 = fmaf(m0, wA0.x, fmaf(m1, wA0.y, fmaf(ct2, wA0.z, fmaf(m3, wA0.w, acc0))));
            acc1 = fmaf(m0, wA1.x, fmaf(m1, wA1.y, fmaf(ct2, wA1.z, fmaf(m3, wA1.w, acc1))));
        }
        // patch B: t = (r0.z, r0.w, r1.z, r1.w)
        {
            float s0, c0, sa, ca;
            __sincosf(r0.z, &s0, &c0);
            __sincosf(r0.w + P1, &sa, &ca);
            const float ct2 = __cosf(r1.z);
            const float ct3 = __cosf(r1.w);
            const float m0 = fmaf(K1, c0, -sp4 * sa * s0);
            const float m1 = cp0 * ca * c0;
            const float m3 = cp3 * ct2 * ct3;
            acc0 = fmaf(m0, wB0.x, fmaf(m1, wB0.y, fmaf(ct2, wB0.z, fmaf(m3, wB0.w, acc0))));
            acc1 = fmaf(m0, wB1.x, fmaf(m1, wB1.y, fmaf(ct2, wB1.z, fmaf(m3, wB1.w, acc1))));
        }
    }

    // intra-warp reduce (fixed order -> deterministic)
#pragma unroll
    for (int off = 16; off > 0; off >>= 1) {
        acc0 += __shfl_down_sync(0xFFFFFFFFu, acc0, off);
        acc1 += __shfl_down_sync(0xFFFFFFFFu, acc1, off);
    }

    __shared__ float2 warpred[BLKT / 32];   // 8 entries
    if ((tid & 31) == 0) warpred[tid >> 5] = make_float2(acc0, acc1);
    __syncthreads();

    if (tid < 32) {
        float2 v = (tid < BLKT / 32) ? warpred[tid] : make_float2(0.f, 0.f);
#pragma unroll
        for (int off = 4; off > 0; off >>= 1) {
            v.x += __shfl_down_sync(0xFFFFFFFFu, v.x, off);
            v.y += __shfl_down_sync(0xFFFFFFFFu, v.y, off);
        }
        if (tid == 0) {
            g_partial[b * SL + slice] = v;
            __threadfence();
            const unsigned int old = atomicAdd(&g_cnt[b], 1u);
            if (old == SL - 1) {           // last block for this image
                g_cnt[b] = 0;              // reset for next graph replay
                // independent (non-chained) loads of the 5 fixed slots
                float2 p0 = __ldcg(&g_partial[b * SL + 0]);
                float2 p1 = __ldcg(&g_partial[b * SL + 1]);
                float2 p2 = __ldcg(&g_partial[b * SL + 2]);
                float2 p3 = __ldcg(&g_partial[b * SL + 3]);
                float2 p4 = __ldcg(&g_partial[b * SL + 4]);
                float l0 = bias[0] + p0.x + p1.x + p2.x + p3.x + p4.x;
                float l1 = bias[1] + p0.y + p1.y + p2.y + p3.y + p4.y;
                const float m   = fmaxf(l0, l1);
                const float lse = m + __logf(__expf(l0 - m) + __expf(l1 - m));
                out[b * 2 + 0] = l0 - lse;
                out[b * 2 + 1] = l1 - lse;
            }
        }
    }
}

extern "C" void kernel_launch(void* const* d_in, const int* in_sizes, int n_in,
                              void* d_out, int out_size)
{
    (void)in_sizes; (void)n_in; (void)out_size;
    const float* x    = (const float*)d_in[0];  // [64,100,100]
    const float* W    = (const float*)d_in[1];  // [2,10000]
    const float* bias = (const float*)d_in[2];  // [2]
    const float* qp   = (const float*)d_in[3];  // [6]

    dim3 grid(SL, 64);
    fused_kernel<<<grid, BLKT>>>(x, W, bias, qp, (float*)d_out);
}

// round 4
// speedup vs baseline: 1.2899x; 1.2899x over previous
#include <cuda_runtime.h>
#include <math.h>

// Closed-form collapse of the 4-qubit circuit:
//   m0 = cos(p4)cos(p0)cos(t0) - sin(p4)sin(t1+p1)sin(t0)
//   m1 = cos(t1+p1)cos(p0)cos(t0)
//   m2 = cos(t2)
//   m3 = cos(p3)cos(t2)cos(t3)
// logits[b,k] = sum_patch m.W[k] + bias[k]; out = log_softmax(logits).
//
// grid=64 (one block per image), 640 threads; threads 0..624 each handle
// exactly two patch-pairs (4 patches). All loads issued up front for MLP.

#define BLK    640
#define ACTIVE 625     // 1250 pairs / 2

__device__ __forceinline__ void patch_dot(
    float t0, float t1, float t2, float t3,
    float K1, float sp4, float cp0, float cp3, float P1,
    const float4& w0, const float4& w1,
    float& acc0, float& acc1)
{
    float s0, c0, sa, ca;
    __sincosf(t0, &s0, &c0);
    __sincosf(t1 + P1, &sa, &ca);
    const float ct2 = __cosf(t2);
    const float ct3 = __cosf(t3);
    const float m0 = fmaf(K1, c0, -sp4 * sa * s0);
    const float m1 = cp0 * ca * c0;
    const float m3 = cp3 * ct2 * ct3;
    acc0 = fmaf(m0, w0.x, fmaf(m1, w0.y, fmaf(ct2, w0.z, fmaf(m3, w0.w, acc0))));
    acc1 = fmaf(m0, w1.x, fmaf(m1, w1.y, fmaf(ct2, w1.z, fmaf(m3, w1.w, acc1))));
}

__global__ __launch_bounds__(BLK) void fused_kernel(
    const float* __restrict__ x,
    const float* __restrict__ W,
    const float* __restrict__ bias,
    const float* __restrict__ qp,
    float* __restrict__ out)
{
    const int tid = threadIdx.x;
    const int b   = blockIdx.x;

    // Circuit constants (broadcast loads; MUFU overlaps x-load latency)
    float sp4, cp4;
    __sincosf(qp[4], &sp4, &cp4);
    const float cp0 = __cosf(qp[0]);
    const float cp3 = __cosf(qp[3]);
    const float P1  = qp[1];
    const float K1  = cp4 * cp0;

    float acc0 = 0.f, acc1 = 0.f;

    if (tid < ACTIVE) {
        const float* xb = x + b * 10000;

        // pair A = tid, pair B = tid + 625
        const int qA  = tid;
        const int qB  = tid + ACTIVE;
        const int iA  = qA / 25, jpA = qA - iA * 25;
        const int iB  = qB / 25, jpB = qB - iB * 25;
        const int pA  = iA * 50 + 2 * jpA;
        const int pB  = iB * 50 + 2 * jpB;

        // ---- issue ALL loads up front (12 independent 16B loads) ----
        const float4 rA0 = *reinterpret_cast<const float4*>(xb + 200 * iA + 4 * jpA);
        const float4 rA1 = *reinterpret_cast<const float4*>(xb + 200 * iA + 100 + 4 * jpA);
        const float4 rB0 = *reinterpret_cast<const float4*>(xb + 200 * iB + 4 * jpB);
        const float4 rB1 = *reinterpret_cast<const float4*>(xb + 200 * iB + 100 + 4 * jpB);
        const float4 wA00 = *reinterpret_cast<const float4*>(W + pA * 4);
        const float4 wA01 = *reinterpret_cast<const float4*>(W + pA * 4 + 4);
        const float4 wA10 = *reinterpret_cast<const float4*>(W + 10000 + pA * 4);
        const float4 wA11 = *reinterpret_cast<const float4*>(W + 10000 + pA * 4 + 4);
        const float4 wB00 = *reinterpret_cast<const float4*>(W + pB * 4);
        const float4 wB01 = *reinterpret_cast<const float4*>(W + pB * 4 + 4);
        const float4 wB10 = *reinterpret_cast<const float4*>(W + 10000 + pB * 4);
        const float4 wB11 = *reinterpret_cast<const float4*>(W + 10000 + pB * 4 + 4);

        // pair A, patch 0 and 1
        patch_dot(rA0.x, rA0.y, rA1.x, rA1.y, K1, sp4, cp0, cp3, P1, wA00, wA10, acc0, acc1);
        patch_dot(rA0.z, rA0.w, rA1.z, rA1.w, K1, sp4, cp0, cp3, P1, wA01, wA11, acc0, acc1);
        // pair B, patch 0 and 1
        patch_dot(rB0.x, rB0.y, rB1.x, rB1.y, K1, sp4, cp0, cp3, P1, wB00, wB10, acc0, acc1);
        patch_dot(rB0.z, rB0.w, rB1.z, rB1.w, K1, sp4, cp0, cp3, P1, wB01, wB11, acc0, acc1);
    }

    // deterministic reduction: warp shuffle -> smem -> warp 0 shuffle
#pragma unroll
    for (int off = 16; off > 0; off >>= 1) {
        acc0 += __shfl_down_sync(0xFFFFFFFFu, acc0, off);
        acc1 += __shfl_down_sync(0xFFFFFFFFu, acc1, off);
    }

    __shared__ float2 warpred[BLK / 32];   // 20 entries
    if ((tid & 31) == 0) warpred[tid >> 5] = make_float2(acc0, acc1);
    __syncthreads();

    if (tid < 32) {
        float2 v = (tid < BLK / 32) ? warpred[tid] : make_float2(0.f, 0.f);
#pragma unroll
        for (int off = 16; off > 0; off >>= 1) {
            v.x += __shfl_down_sync(0xFFFFFFFFu, v.x, off);
            v.y += __shfl_down_sync(0xFFFFFFFFu, v.y, off);
        }
        if (tid == 0) {
            const float l0 = bias[0] + v.x;
            const float l1 = bias[1] + v.y;
            const float m   = fmaxf(l0, l1);
            const float lse = m + __logf(__expf(l0 - m) + __expf(l1 - m));
            out[b * 2 + 0] = l0 - lse;
            out[b * 2 + 1] = l1 - lse;
        }
    }
}

extern "C" void kernel_launch(void* const* d_in, const int* in_sizes, int n_in,
                              void* d_out, int out_size)
{
    (void)in_sizes; (void)n_in; (void)out_size;
    const float* x    = (const float*)d_in[0];  // [64,100,100]
    const float* W    = (const float*)d_in[1];  // [2,10000]
    const float* bias = (const float*)d_in[2];  // [2]
    const float* qp   = (const float*)d_in[3];  // [6]

    fused_kernel<<<64, BLK>>>(x, W, bias, qp, (float*)d_out);
}